// round 15
// baseline (speedup 1.0000x reference)
#include <cuda_runtime.h>
#include <cuda_bf16.h>
#include <cuda_fp16.h>
#include <cstdint>
#include <math.h>

// ---------------- problem constants ----------------
#define BB 16
#define SS 1024
#define DD 1024
#define HH 8
#define QKD 128
#define EXPD 2048
#define NROWS (BB*SS)    // 16384
#define EOUT (2*QKD + 2*EXPD)  // 4352
#define LOG2E 1.4426950408889634f

// ---------------- scratch ----------------
__device__ __nv_bfloat16 g_xn[(size_t)NROWS * DD];
__device__ __nv_bfloat16 g_qk[(size_t)NROWS * 256];       // [q(128, pre-scaled by 0.25*log2e) | k(128)]
__device__ __nv_bfloat16 g_concat[(size_t)NROWS * EXPD];  // [0,1024): geglu_local, [1024,2048): attention
__device__ __half g_v[(size_t)NROWS * DD];                // V in f16
__device__ __nv_bfloat16 g_wexp[(size_t)EOUT * DD];       // reordered: [q,k | interleaved lin/pre]
__device__ __nv_bfloat16 g_wproj[(size_t)DD * EXPD];

// ---------------- helpers ----------------
__device__ __forceinline__ void mma16816(float d[4], const uint32_t a[4], const uint32_t b[2]) {
    asm volatile(
        "mma.sync.aligned.m16n8k16.row.col.f32.bf16.bf16.f32 "
        "{%0,%1,%2,%3},{%4,%5,%6,%7},{%8,%9},{%0,%1,%2,%3};\n"
        : "+f"(d[0]), "+f"(d[1]), "+f"(d[2]), "+f"(d[3])
        : "r"(a[0]), "r"(a[1]), "r"(a[2]), "r"(a[3]), "r"(b[0]), "r"(b[1]));
}

__device__ __forceinline__ void mma16816h(float d[4], const uint32_t a[4], const uint32_t b[2]) {
    asm volatile(
        "mma.sync.aligned.m16n8k16.row.col.f32.f16.f16.f32 "
        "{%0,%1,%2,%3},{%4,%5,%6,%7},{%8,%9},{%0,%1,%2,%3};\n"
        : "+f"(d[0]), "+f"(d[1]), "+f"(d[2]), "+f"(d[3])
        : "r"(a[0]), "r"(a[1]), "r"(a[2]), "r"(a[3]), "r"(b[0]), "r"(b[1]));
}

__device__ __forceinline__ void ldsm4(uint32_t r[4], uint32_t saddr) {
    asm volatile("ldmatrix.sync.aligned.m8n8.x4.shared.b16 {%0,%1,%2,%3}, [%4];"
                 : "=r"(r[0]), "=r"(r[1]), "=r"(r[2]), "=r"(r[3]) : "r"(saddr));
}

__device__ __forceinline__ void ldsm4t(uint32_t r[4], uint32_t saddr) {
    asm volatile("ldmatrix.sync.aligned.m8n8.x4.trans.shared.b16 {%0,%1,%2,%3}, [%4];"
                 : "=r"(r[0]), "=r"(r[1]), "=r"(r[2]), "=r"(r[3]) : "r"(saddr));
}

__device__ __forceinline__ void cp16(uint32_t saddr, const void* g) {
    asm volatile("cp.async.cg.shared.global [%0], [%1], 16;" :: "r"(saddr), "l"(g));
}

// pack two f32 -> f16x2 (lo in low half)
__device__ __forceinline__ __half2 packh2(float lo, float hi) {
    __half2 r;
    asm("cvt.rn.f16x2.f32 %0, %1, %2;" : "=r"(*(uint32_t*)&r) : "f"(hi), "f"(lo));
    return r;
}

__device__ __forceinline__ float gelu_exact(float p) {
    return 0.5f * p * (1.f + erff(p * 0.70710678118654752f));
}

// ---------------- weight converts ----------------
__global__ void cvt_kernel(const float* __restrict__ src, __nv_bfloat16* __restrict__ dst, int n4) {
    int i = blockIdx.x * blockDim.x + threadIdx.x;
    if (i < n4) {
        float4 v = ((const float4*)src)[i];
        __nv_bfloat162* d = (__nv_bfloat162*)(dst + (size_t)i * 4);
        d[0] = __floats2bfloat162_rn(v.x, v.y);
        d[1] = __floats2bfloat162_rn(v.z, v.w);
    }
}

// expand_w convert + row reorder (lin/pre interleave)
__global__ void cvt_exp_kernel(const float* __restrict__ src, __nv_bfloat16* __restrict__ dst) {
    int i = blockIdx.x * blockDim.x + threadIdx.x;   // over EOUT * (DD/4)
    int r = i >> 8;
    int c4 = i & 255;
    int t = r - 256;
    int sr = (r < 256) ? r : ((t & 1) ? (2304 + (t >> 1)) : (256 + (t >> 1)));
    float4 v = ((const float4*)(src + (size_t)sr * DD))[c4];
    __nv_bfloat162* d = (__nv_bfloat162*)(dst + (size_t)r * DD + c4 * 4);
    d[0] = __floats2bfloat162_rn(v.x, v.y);
    d[1] = __floats2bfloat162_rn(v.z, v.w);
}

// ---------------- LayerNorm ----------------
__global__ __launch_bounds__(256) void ln_kernel(const float* __restrict__ x,
                                                 const float* __restrict__ w,
                                                 __nv_bfloat16* __restrict__ out) {
    int row = blockIdx.x;
    float4 v = ((const float4*)(x + (size_t)row * DD))[threadIdx.x];
    float s = v.x + v.y + v.z + v.w;
    float s2 = v.x * v.x + v.y * v.y + v.z * v.z + v.w * v.w;
#pragma unroll
    for (int o = 16; o; o >>= 1) {
        s += __shfl_xor_sync(0xffffffffu, s, o);
        s2 += __shfl_xor_sync(0xffffffffu, s2, o);
    }
    __shared__ float rs[8], rs2[8];
    int warp = threadIdx.x >> 5, lane = threadIdx.x & 31;
    if (!lane) { rs[warp] = s; rs2[warp] = s2; }
    __syncthreads();
    if (threadIdx.x == 0) {
        float a = 0.f, b = 0.f;
#pragma unroll
        for (int i = 0; i < 8; i++) { a += rs[i]; b += rs2[i]; }
        rs[0] = a; rs2[0] = b;
    }
    __syncthreads();
    float mu = rs[0] * (1.f / DD);
    float var = rs2[0] * (1.f / DD) - mu * mu;
    float r = rsqrtf(var + 1e-5f);
    float4 w4 = ((const float4*)w)[threadIdx.x];
    __nv_bfloat16* op = out + (size_t)row * DD + threadIdx.x * 4;
    *(__nv_bfloat162*)op = __floats2bfloat162_rn((v.x - mu) * r * w4.x, (v.y - mu) * r * w4.y);
    *(__nv_bfloat162*)(op + 2) = __floats2bfloat162_rn((v.z - mu) * r * w4.z, (v.w - mu) * r * w4.w);
}

// ---------------- bf16 GEMM (round-14 best, unchanged) ----------------
#define GSTG 3
#define GSTAGE_BYTES (128 * 64 * 2)
#define GSMEM_BYTES (2 * GSTG * GSTAGE_BYTES)

template <int MODE, int KK>
__global__ __launch_bounds__(256, 2) void gemm_bf16(const __nv_bfloat16* __restrict__ A,
                                                    const __nv_bfloat16* __restrict__ Bw,
                                                    __nv_bfloat16* __restrict__ qk,
                                                    __nv_bfloat16* __restrict__ concat,
                                                    __half* __restrict__ vbuf,
                                                    const float* __restrict__ resid,
                                                    float* __restrict__ Cf) {
    extern __shared__ __nv_bfloat16 smbuf[];
    const int tid = threadIdx.x;
    const int warp = tid >> 5, lane = tid & 31;
    const int gid = lane >> 2, tig = lane & 3;
    const int wm = (warp >> 2) * 64, wn = (warp & 3) * 32;
    const int bm = blockIdx.y, bn = blockIdx.x;

    const uint32_t sbase = (uint32_t)__cvta_generic_to_shared(smbuf);

    const int r = tid >> 3, c = tid & 7;
    const int swz = (c ^ (r & 7)) * 16;
    const __nv_bfloat16* Ag = A + ((size_t)(bm * 128 + r)) * KK + c * 8;
    const __nv_bfloat16* Bg = Bw + ((size_t)(bn * 128 + r)) * KK + c * 8;

    auto load_stage = [&](int s, int kt) {
        uint32_t sa = sbase + s * GSTAGE_BYTES + r * 128 + swz;
        uint32_t sb = sbase + GSTG * GSTAGE_BYTES + s * GSTAGE_BYTES + r * 128 + swz;
        const __nv_bfloat16* ag = Ag + kt * 64;
        const __nv_bfloat16* bg = Bg + kt * 64;
#pragma unroll
        for (int it = 0; it < 4; it++) {
            cp16(sa + it * 32 * 128, ag + (size_t)(it * 32) * KK);
            cp16(sb + it * 32 * 128, bg + (size_t)(it * 32) * KK);
        }
    };

    float acc[4][4][4];
#pragma unroll
    for (int i = 0; i < 4; i++)
#pragma unroll
        for (int j = 0; j < 4; j++)
#pragma unroll
            for (int q = 0; q < 4; q++) acc[i][j][q] = 0.f;

    load_stage(0, 0);
    asm volatile("cp.async.commit_group;" ::: "memory");
    load_stage(1, 1);
    asm volatile("cp.async.commit_group;" ::: "memory");

    const int a_lrow = lane & 15;
    const int a_chi = lane >> 4;
    const int b_lrow = (lane & 7) + ((lane >> 4) << 3);
    const int b_chi = (lane >> 3) & 1;

    constexpr int KT = KK >> 6;
#pragma unroll 1
    for (int kt = 0; kt < KT; kt++) {
        asm volatile("cp.async.wait_group 1;" ::: "memory");
        __syncthreads();

        const bool pf = (kt + 2 < KT);
        const int ns = (kt + 2) % GSTG;
        const uint32_t pa_s = sbase + ns * GSTAGE_BYTES + r * 128 + swz;
        const uint32_t pb_s = pa_s + GSTG * GSTAGE_BYTES;
        const __nv_bfloat16* pag = Ag + (kt + 2) * 64;
        const __nv_bfloat16* pbg = Bg + (kt + 2) * 64;

        const uint32_t sA = sbase + (kt % GSTG) * GSTAGE_BYTES;
        const uint32_t sB = sA + GSTG * GSTAGE_BYTES;
#pragma unroll
        for (int ks = 0; ks < 4; ks++) {
            uint32_t af[4][4], bfr[4][2];
#pragma unroll
            for (int mi = 0; mi < 4; mi++) {
                int row = wm + mi * 16 + a_lrow;
                int cc = ks * 2 + a_chi;
                ldsm4(af[mi], sA + row * 128 + ((cc ^ (row & 7)) * 16));
            }
#pragma unroll
            for (int j = 0; j < 2; j++) {
                int row = wn + j * 16 + b_lrow;
                int cc = ks * 2 + b_chi;
                uint32_t rr[4];
                ldsm4(rr, sB + row * 128 + ((cc ^ (row & 7)) * 16));
                bfr[j * 2][0] = rr[0]; bfr[j * 2][1] = rr[1];
                bfr[j * 2 + 1][0] = rr[2]; bfr[j * 2 + 1][1] = rr[3];
            }
            if (pf) {
                cp16(pa_s + ks * 32 * 128, pag + (size_t)(ks * 32) * KK);
                cp16(pb_s + ks * 32 * 128, pbg + (size_t)(ks * 32) * KK);
            }
#pragma unroll
            for (int mi = 0; mi < 4; mi++)
#pragma unroll
                for (int ni = 0; ni < 4; ni++) mma16816(acc[mi][ni], af[mi], bfr[ni]);
        }
        asm volatile("cp.async.commit_group;" ::: "memory");
    }

    const float QSCALE = 0.25f * LOG2E;
#pragma unroll
    for (int mi = 0; mi < 4; mi++) {
        int r0 = bm * 128 + wm + mi * 16 + gid;
#pragma unroll
        for (int ni = 0; ni < 4; ni++) {
            int col = bn * 128 + wn + ni * 8 + tig * 2;
            if (MODE == 1) {
                size_t i0 = (size_t)r0 * DD + col;
                size_t i1 = (size_t)(r0 + 8) * DD + col;
                float2 v0 = make_float2(acc[mi][ni][0] + resid[i0], acc[mi][ni][1] + resid[i0 + 1]);
                float2 v1 = make_float2(acc[mi][ni][2] + resid[i1], acc[mi][ni][3] + resid[i1 + 1]);
                *(float2*)&Cf[i0] = v0;
                *(float2*)&Cf[i1] = v1;
            } else {
                if (bn < 2) {
                    float f = (bn == 0) ? QSCALE : 1.f;
                    *(__nv_bfloat162*)&qk[(size_t)r0 * 256 + col] =
                        __floats2bfloat162_rn(acc[mi][ni][0] * f, acc[mi][ni][1] * f);
                    *(__nv_bfloat162*)&qk[(size_t)(r0 + 8) * 256 + col] =
                        __floats2bfloat162_rn(acc[mi][ni][2] * f, acc[mi][ni][3] * f);
                } else {
                    int e = (col - 256) >> 1;
                    float v0 = acc[mi][ni][0] * gelu_exact(acc[mi][ni][1]);
                    float v1 = acc[mi][ni][2] * gelu_exact(acc[mi][ni][3]);
                    if (e < 1024) {
                        concat[(size_t)r0 * EXPD + e] = __float2bfloat16(v0);
                        concat[(size_t)(r0 + 8) * EXPD + e] = __float2bfloat16(v1);
                    } else {
                        vbuf[(size_t)r0 * DD + e - 1024] = __float2half(v0);
                        vbuf[(size_t)(r0 + 8) * DD + e - 1024] = __float2half(v1);
                    }
                }
            }
        }
    }
}

// ---------------- flash attention: q-tile 256, 512 threads (16 warps), f16 shift-softmax ----
#define AKS_B 6144                         // Ks stage: 128 rows * 48B
#define AVS_B 32768                        // Vs stage: 128 rows * 256B
#define AST_B (AKS_B + AVS_B)
#define ATT_SMEM (2 * AST_B)               // 77824

__global__ __launch_bounds__(512) void attn_kernel(const __nv_bfloat16* __restrict__ qk,
                                                   const __half* __restrict__ vbuf,
                                                   __nv_bfloat16* __restrict__ concat,
                                                   const float* __restrict__ pbm_p,
                                                   const int* __restrict__ fi_p,
                                                   const int* __restrict__ li_p) {
    extern __shared__ __align__(16) char asmem[];
    const int tid = threadIdx.x, warp = tid >> 5, lane = tid & 31;
    const int gid = lane >> 2, tig = lane & 3;
    const int bh = blockIdx.y, b = bh >> 3, h = bh & 7;
    const int qbase = blockIdx.x * 256;
    float pbm = *pbm_p;
    const float sp_l2 = (fmaxf(pbm, 0.f) + log1pf(expf(-fabsf(pbm)))) * LOG2E;
    int fi = *fi_p; if (fi >= SS) fi = 0;
    int li = *li_p; if (li >= SS) li = 0;

    const uint32_t abase = (uint32_t)__cvta_generic_to_shared(asmem);

    const int i0 = qbase + warp * 16 + gid;
    const int i1 = i0 + 8;
    uint32_t qa[4];
    {
        const size_t base = ((size_t)(b * SS + i0)) * 256 + h * 16 + tig * 2;
        qa[0] = *(const uint32_t*)&qk[base];
        qa[1] = *(const uint32_t*)&qk[base + 8 * 256];
        qa[2] = *(const uint32_t*)&qk[base + 8];
        qa[3] = *(const uint32_t*)&qk[base + 8 * 256 + 8];
    }
    float m0 = -1e30f, m1 = -1e30f;
    float o[16][4];
#pragma unroll
    for (int ni = 0; ni < 16; ni++)
#pragma unroll
        for (int r = 0; r < 4; r++) o[ni][r] = 0.f;
    float o_l[4] = {0.f, 0.f, 0.f, 0.f};  // ones-column: row sums

    const int qmax = qbase + 255;
    const int l15 = lane & 15, lhi = lane >> 4;
    const int kb = (lane & 7) + ((lane >> 4) << 3);   // QK B-frag ldsm row
    const int kcc = (lane >> 3) & 1;                  // QK B-frag 16B chunk

    int list[8];
    int n = 0;
#pragma unroll
    for (int kc = 0; kc < 8; kc++) {
        int kmin = kc * 128;
        if (kmin <= qmax || ((qmax >= fi) && (kmin + 127 >= li))) list[n++] = kc;
    }

    // 512 threads: K (256 cp16) by tid<256; V (2048 cp16) 4 per thread
    const int krow = tid >> 1, khalf = tid & 1;
    const int vr = tid >> 2, vq = tid & 3;
    auto load_chunk = [&](int st, int kmin) {
        uint32_t ks = abase + st * AST_B;
        uint32_t vs = ks + AKS_B;
        if (tid < 256)
            cp16(ks + krow * 48 + khalf * 16,
                 &qk[((size_t)(b * SS + kmin + krow)) * 256 + 128 + h * 16 + khalf * 8]);
        const __half* src = &vbuf[((size_t)(b * SS + kmin + vr)) * DD + h * 128];
        uint32_t drow = vs + vr * 256;
        int rsw = vr & 15;
#pragma unroll
        for (int j = 0; j < 4; j++) {
            int cc = vq * 4 + j;
            cp16(drow + ((cc ^ rsw) << 4), src + cc * 8);
        }
    };

    const uint32_t bones[2] = {0x3C003C00u, 0x3C003C00u};  // f16 ones

    load_chunk(0, list[0] * 128);
    asm volatile("cp.async.commit_group;" ::: "memory");

    for (int t = 0; t < n; t++) {
        const int kmin = list[t] * 128;
        const int st = t & 1;
        if (t + 1 < n) {
            load_chunk((t + 1) & 1, list[t + 1] * 128);
            asm volatile("cp.async.commit_group;" ::: "memory");
            asm volatile("cp.async.wait_group 1;" ::: "memory");
        } else {
            asm volatile("cp.async.wait_group 0;" ::: "memory");
        }
        __syncthreads();

        const uint32_t ksb = abase + st * AST_B;
        const uint32_t vsb = ksb + AKS_B;
        const int km127 = kmin + 127;

        // per-row visible-j maximum (mask structure only) -> shift so packed scores are O(1)
        const bool fast = (km127 < qbase);            // fully visible for every row in tile
        const bool covr = (km127 >= li);
        int jm0, jm1;
        if (fast) { jm0 = km127; jm1 = km127; }
        else {
            jm0 = ((i0 >= fi) && covr) ? km127 : min(i0, km127);
            jm1 = ((i1 >= fi) && covr) ? km127 : min(i1, km127);
        }
        const float off0 = sp_l2 * (float)(jm0 - i0);
        const float off1 = sp_l2 * (float)(jm1 - i1);

        // QK^T with immediate bias/mask + f16x2 pack (scores never live as f32 array)
        __half2 pk0[16], pk1[16];
#pragma unroll
        for (int ni2 = 0; ni2 < 8; ni2++) {
            uint32_t rr[4];
            ldsm4(rr, ksb + (ni2 * 16 + kb) * 48 + kcc * 16);
#pragma unroll
            for (int tt = 0; tt < 2; tt++) {
                const int ni = 2 * ni2 + tt;
                float d[4] = {0.f, 0.f, 0.f, 0.f};
                uint32_t bf[2] = {rr[2 * tt], rr[2 * tt + 1]};
                mma16816(d, qa, bf);
                const int jc = kmin + ni * 8 + tig * 2;
                if (fast) {
                    float bb = sp_l2 * (float)(jc - km127);
                    d[0] += bb; d[1] += bb + sp_l2;
                    d[2] += bb; d[3] += bb + sp_l2;
                } else {
#pragma unroll
                    for (int rr2 = 0; rr2 < 4; rr2++) {
                        int j = jc + (rr2 & 1);
                        int i = (rr2 < 2) ? i0 : i1;
                        int jm = (rr2 < 2) ? jm0 : jm1;
                        bool ok = (j <= i) || ((i >= fi) && covr && (j >= li));
                        d[rr2] = ok ? fmaf(sp_l2, (float)(j - jm), d[rr2]) : -1e30f;
                    }
                }
                pk0[ni] = packh2(d[0], d[1]);
                pk1[ni] = packh2(d[2], d[3]);
            }
        }

        // row max over packed scores
        __half2 hm0 = pk0[0], hm1 = pk1[0];
#pragma unroll
        for (int ni = 1; ni < 16; ni++) {
            hm0 = __hmax2(hm0, pk0[ni]);
            hm1 = __hmax2(hm1, pk1[ni]);
        }
        float rp0 = fmaxf(__low2float(hm0), __high2float(hm0));
        float rp1 = fmaxf(__low2float(hm1), __high2float(hm1));
        rp0 = fmaxf(rp0, __shfl_xor_sync(0xffffffffu, rp0, 1));
        rp0 = fmaxf(rp0, __shfl_xor_sync(0xffffffffu, rp0, 2));
        rp1 = fmaxf(rp1, __shfl_xor_sync(0xffffffffu, rp1, 1));
        rp1 = fmaxf(rp1, __shfl_xor_sync(0xffffffffu, rp1, 2));
        const float mn0 = fmaxf(m0, rp0 + off0);
        const float mn1 = fmaxf(m1, rp1 + off1);
        const float cor0 = exp2f(m0 - mn0), cor1 = exp2f(m1 - mn1);
        m0 = mn0; m1 = mn1;
#pragma unroll
        for (int ni = 0; ni < 16; ni++) {
            o[ni][0] *= cor0; o[ni][1] *= cor0; o[ni][2] *= cor1; o[ni][3] *= cor1;
        }
        o_l[0] *= cor0; o_l[1] *= cor0; o_l[2] *= cor1; o_l[3] *= cor1;

        // P = exp2(packed - (m - off)), all in f16x2
        const __half2 mb0 = __float2half2_rn(mn0 - off0);
        const __half2 mb1 = __float2half2_rn(mn1 - off1);
#pragma unroll
        for (int ni = 0; ni < 16; ni++) {
            pk0[ni] = h2exp2(__hsub2(pk0[ni], mb0));
            pk1[ni] = h2exp2(__hsub2(pk1[ni], mb1));
        }

        // PV (f16) + ones-column row sums
        const uint32_t vrow = vsb + l15 * 256;
#pragma unroll
        for (int ks = 0; ks < 8; ks++) {
            uint32_t pa[4] = {*(uint32_t*)&pk0[2 * ks], *(uint32_t*)&pk1[2 * ks],
                              *(uint32_t*)&pk0[2 * ks + 1], *(uint32_t*)&pk1[2 * ks + 1]};
            mma16816h(o_l, pa, bones);
            const uint32_t kofs = vrow + ks * 4096;
#pragma unroll
            for (int ni2 = 0; ni2 < 8; ni2++) {
                uint32_t rr[4];
                ldsm4t(rr, kofs + (((ni2 * 2 + lhi) ^ l15) << 4));
                uint32_t b0[2] = {rr[0], rr[1]};
                uint32_t b1[2] = {rr[2], rr[3]};
                mma16816h(o[2 * ni2], pa, b0);
                mma16816h(o[2 * ni2 + 1], pa, b1);
            }
        }
        __syncthreads();
    }

    float inv0 = 1.f / o_l[0], inv1 = 1.f / o_l[2];
#pragma unroll
    for (int ni = 0; ni < 16; ni++) {
        int col = 1024 + h * 128 + ni * 8 + tig * 2;
        *(__nv_bfloat162*)&concat[((size_t)(b * SS) + i0) * EXPD + col] =
            __floats2bfloat162_rn(o[ni][0] * inv0, o[ni][1] * inv0);
        *(__nv_bfloat162*)&concat[((size_t)(b * SS) + i1) * EXPD + col] =
            __floats2bfloat162_rn(o[ni][2] * inv1, o[ni][3] * inv1);
    }
}

// ---------------- launch ----------------
extern "C" void kernel_launch(void* const* d_in, const int* in_sizes, int n_in,
                              void* d_out, int out_size) {
    const float* x = (const float*)d_in[0];
    const float* norm_w = (const float*)d_in[1];
    const float* expand_w = (const float*)d_in[2];
    const float* project_w = (const float*)d_in[3];
    const float* pbm = (const float*)d_in[4];
    const int* fi = (const int*)d_in[5];
    const int* li = (const int*)d_in[6];
    float* out = (float*)d_out;

    void *p_xn, *p_qk, *p_concat, *p_v, *p_wexp, *p_wproj;
    cudaGetSymbolAddress(&p_xn, g_xn);
    cudaGetSymbolAddress(&p_qk, g_qk);
    cudaGetSymbolAddress(&p_concat, g_concat);
    cudaGetSymbolAddress(&p_v, g_v);
    cudaGetSymbolAddress(&p_wexp, g_wexp);
    cudaGetSymbolAddress(&p_wproj, g_wproj);
    __nv_bfloat16* xn = (__nv_bfloat16*)p_xn;
    __nv_bfloat16* qk = (__nv_bfloat16*)p_qk;
    __nv_bfloat16* concat = (__nv_bfloat16*)p_concat;
    __half* vb = (__half*)p_v;
    __nv_bfloat16* wexp = (__nv_bfloat16*)p_wexp;
    __nv_bfloat16* wproj = (__nv_bfloat16*)p_wproj;

    cudaFuncSetAttribute(gemm_bf16<0, 1024>, cudaFuncAttributeMaxDynamicSharedMemorySize, GSMEM_BYTES);
    cudaFuncSetAttribute(gemm_bf16<1, 2048>, cudaFuncAttributeMaxDynamicSharedMemorySize, GSMEM_BYTES);
    cudaFuncSetAttribute(attn_kernel, cudaFuncAttributeMaxDynamicSharedMemorySize, ATT_SMEM);

    // weights -> bf16
    cvt_exp_kernel<<<EOUT * (DD / 4) / 256, 256>>>(expand_w, wexp);
    cvt_kernel<<<(DD * EXPD / 4 + 255) / 256, 256>>>(project_w, wproj, DD * EXPD / 4);

    // layernorm
    ln_kernel<<<NROWS, 256>>>(x, norm_w, xn);

    // expand GEMM fused with geglu: qk (q pre-scaled) + concat[:, :1024] + vbuf (f16)
    gemm_bf16<0, 1024><<<dim3(EOUT / 128, NROWS / 128), 256, GSMEM_BYTES>>>(
        xn, wexp, qk, concat, vb, nullptr, nullptr);

    // attention (q-tile 256, 512 threads) -> concat[:, 1024:2048]
    attn_kernel<<<dim3(SS / 256, BB * HH), 512, ATT_SMEM>>>(qk, vb, concat, pbm, fi, li);

    // project GEMM + residual: out = concat @ wproj^T + x
    gemm_bf16<1, 2048><<<dim3(DD / 128, NROWS / 128), 256, GSMEM_BYTES>>>(
        concat, wproj, nullptr, nullptr, nullptr, x, out);
}

// round 16
// speedup vs baseline: 1.0600x; 1.0600x over previous
#include <cuda_runtime.h>
#include <cuda_bf16.h>
#include <cuda_fp16.h>
#include <cstdint>
#include <math.h>

// ---------------- problem constants ----------------
#define BB 16
#define SS 1024
#define DD 1024
#define HH 8
#define QKD 128
#define EXPD 2048
#define NROWS (BB*SS)    // 16384
#define EOUT (2*QKD + 2*EXPD)  // 4352
#define LOG2E 1.4426950408889634f

// ---------------- scratch ----------------
__device__ __nv_bfloat16 g_xn[(size_t)NROWS * DD];
__device__ __nv_bfloat16 g_qk[(size_t)NROWS * 256];       // [q(128, pre-scaled by 0.25*log2e) | k(128)]
__device__ __nv_bfloat16 g_concat[(size_t)NROWS * EXPD];  // [0,1024): geglu_local, [1024,2048): attention
__device__ __half g_v[(size_t)NROWS * DD];                // V in f16
__device__ __nv_bfloat16 g_wexp[(size_t)EOUT * DD];       // reordered: [q,k | interleaved lin/pre]
__device__ __nv_bfloat16 g_wproj[(size_t)DD * EXPD];

// ---------------- helpers ----------------
__device__ __forceinline__ void mma16816(float d[4], const uint32_t a[4], const uint32_t b[2]) {
    asm volatile(
        "mma.sync.aligned.m16n8k16.row.col.f32.bf16.bf16.f32 "
        "{%0,%1,%2,%3},{%4,%5,%6,%7},{%8,%9},{%0,%1,%2,%3};\n"
        : "+f"(d[0]), "+f"(d[1]), "+f"(d[2]), "+f"(d[3])
        : "r"(a[0]), "r"(a[1]), "r"(a[2]), "r"(a[3]), "r"(b[0]), "r"(b[1]));
}

__device__ __forceinline__ void mma16816h(float d[4], const uint32_t a[4], const uint32_t b[2]) {
    asm volatile(
        "mma.sync.aligned.m16n8k16.row.col.f32.f16.f16.f32 "
        "{%0,%1,%2,%3},{%4,%5,%6,%7},{%8,%9},{%0,%1,%2,%3};\n"
        : "+f"(d[0]), "+f"(d[1]), "+f"(d[2]), "+f"(d[3])
        : "r"(a[0]), "r"(a[1]), "r"(a[2]), "r"(a[3]), "r"(b[0]), "r"(b[1]));
}

__device__ __forceinline__ void ldsm4(uint32_t r[4], uint32_t saddr) {
    asm volatile("ldmatrix.sync.aligned.m8n8.x4.shared.b16 {%0,%1,%2,%3}, [%4];"
                 : "=r"(r[0]), "=r"(r[1]), "=r"(r[2]), "=r"(r[3]) : "r"(saddr));
}

__device__ __forceinline__ void ldsm4t(uint32_t r[4], uint32_t saddr) {
    asm volatile("ldmatrix.sync.aligned.m8n8.x4.trans.shared.b16 {%0,%1,%2,%3}, [%4];"
                 : "=r"(r[0]), "=r"(r[1]), "=r"(r[2]), "=r"(r[3]) : "r"(saddr));
}

__device__ __forceinline__ void cp16(uint32_t saddr, const void* g) {
    asm volatile("cp.async.cg.shared.global [%0], [%1], 16;" :: "r"(saddr), "l"(g));
}

// exp2 of two f32 values -> packed f16x2 probabilities
__device__ __forceinline__ uint32_t exp2_f16x2(float lo, float hi) {
    uint32_t u, p;
    asm("cvt.rn.f16x2.f32 %0, %1, %2;" : "=r"(u) : "f"(hi), "f"(lo));
    asm("ex2.approx.f16x2 %0, %1;" : "=r"(p) : "r"(u));
    return p;
}

__device__ __forceinline__ float gelu_exact(float p) {
    return 0.5f * p * (1.f + erff(p * 0.70710678118654752f));
}

// ---------------- merged weight convert (wexp reorder + wproj) ----------------
#define WEXP4 (EOUT * DD / 4)      // 1114112
#define WPROJ4 (DD * EXPD / 4)     // 524288
__global__ void cvt_all_kernel(const float* __restrict__ expand_w,
                               const float* __restrict__ project_w,
                               __nv_bfloat16* __restrict__ wexp,
                               __nv_bfloat16* __restrict__ wproj) {
    int i = blockIdx.x * blockDim.x + threadIdx.x;
    if (i < WEXP4) {
        int r = i >> 8;
        int c4 = i & 255;
        int t = r - 256;
        int sr = (r < 256) ? r : ((t & 1) ? (2304 + (t >> 1)) : (256 + (t >> 1)));
        float4 v = ((const float4*)(expand_w + (size_t)sr * DD))[c4];
        __nv_bfloat162* d = (__nv_bfloat162*)(wexp + (size_t)r * DD + c4 * 4);
        d[0] = __floats2bfloat162_rn(v.x, v.y);
        d[1] = __floats2bfloat162_rn(v.z, v.w);
    } else {
        int j = i - WEXP4;
        if (j < WPROJ4) {
            float4 v = ((const float4*)project_w)[j];
            __nv_bfloat162* d = (__nv_bfloat162*)(wproj + (size_t)j * 4);
            d[0] = __floats2bfloat162_rn(v.x, v.y);
            d[1] = __floats2bfloat162_rn(v.z, v.w);
        }
    }
}

// ---------------- LayerNorm ----------------
__global__ __launch_bounds__(256) void ln_kernel(const float* __restrict__ x,
                                                 const float* __restrict__ w,
                                                 __nv_bfloat16* __restrict__ out) {
    int row = blockIdx.x;
    float4 v = ((const float4*)(x + (size_t)row * DD))[threadIdx.x];
    float s = v.x + v.y + v.z + v.w;
    float s2 = v.x * v.x + v.y * v.y + v.z * v.z + v.w * v.w;
#pragma unroll
    for (int o = 16; o; o >>= 1) {
        s += __shfl_xor_sync(0xffffffffu, s, o);
        s2 += __shfl_xor_sync(0xffffffffu, s2, o);
    }
    __shared__ float rs[8], rs2[8];
    int warp = threadIdx.x >> 5, lane = threadIdx.x & 31;
    if (!lane) { rs[warp] = s; rs2[warp] = s2; }
    __syncthreads();
    if (threadIdx.x == 0) {
        float a = 0.f, b = 0.f;
#pragma unroll
        for (int i = 0; i < 8; i++) { a += rs[i]; b += rs2[i]; }
        rs[0] = a; rs2[0] = b;
    }
    __syncthreads();
    float mu = rs[0] * (1.f / DD);
    float var = rs2[0] * (1.f / DD) - mu * mu;
    float r = rsqrtf(var + 1e-5f);
    float4 w4 = ((const float4*)w)[threadIdx.x];
    __nv_bfloat16* op = out + (size_t)row * DD + threadIdx.x * 4;
    *(__nv_bfloat162*)op = __floats2bfloat162_rn((v.x - mu) * r * w4.x, (v.y - mu) * r * w4.y);
    *(__nv_bfloat162*)(op + 2) = __floats2bfloat162_rn((v.z - mu) * r * w4.z, (v.w - mu) * r * w4.w);
}

// ---------------- bf16 GEMM: C[M,N] = A[M,K]*Bw[N,K]^T, K compile-time ----------------
// BM=128, BN=128, BK=64, 256 threads, warps 2x4, warp tile 64x32, 3-stage cp.async.
// Interleaved prefetch with hoisted (pointer-increment) addressing.
#define GSTG 3
#define GSTAGE_BYTES (128 * 64 * 2)
#define GSMEM_BYTES (2 * GSTG * GSTAGE_BYTES)

template <int MODE, int KK>
__global__ __launch_bounds__(256, 2) void gemm_bf16(const __nv_bfloat16* __restrict__ A,
                                                    const __nv_bfloat16* __restrict__ Bw,
                                                    __nv_bfloat16* __restrict__ qk,
                                                    __nv_bfloat16* __restrict__ concat,
                                                    __half* __restrict__ vbuf,
                                                    const float* __restrict__ resid,
                                                    float* __restrict__ Cf) {
    extern __shared__ __nv_bfloat16 smbuf[];
    const int tid = threadIdx.x;
    const int warp = tid >> 5, lane = tid & 31;
    const int gid = lane >> 2, tig = lane & 3;
    const int wm = (warp >> 2) * 64, wn = (warp & 3) * 32;
    const int bm = blockIdx.y, bn = blockIdx.x;

    const uint32_t sbase = (uint32_t)__cvta_generic_to_shared(smbuf);

    const int r = tid >> 3, c = tid & 7;
    const int swz = (c ^ (r & 7)) * 16;
    const __nv_bfloat16* Ag = A + ((size_t)(bm * 128 + r)) * KK + c * 8;
    const __nv_bfloat16* Bg = Bw + ((size_t)(bn * 128 + r)) * KK + c * 8;

    // hoisted per-stage smem bases for the copy lanes
    uint32_t stA[GSTG], stB[GSTG];
#pragma unroll
    for (int s = 0; s < GSTG; s++) {
        stA[s] = sbase + s * GSTAGE_BYTES + r * 128 + swz;
        stB[s] = stA[s] + GSTG * GSTAGE_BYTES;
    }

    auto load_stage = [&](int s, int kt) {
        const __nv_bfloat16* ag = Ag + kt * 64;
        const __nv_bfloat16* bg = Bg + kt * 64;
#pragma unroll
        for (int it = 0; it < 4; it++) {
            cp16(stA[s] + it * 32 * 128, ag + (size_t)(it * 32) * KK);
            cp16(stB[s] + it * 32 * 128, bg + (size_t)(it * 32) * KK);
        }
    };

    float acc[4][4][4];
#pragma unroll
    for (int i = 0; i < 4; i++)
#pragma unroll
        for (int j = 0; j < 4; j++)
#pragma unroll
            for (int q = 0; q < 4; q++) acc[i][j][q] = 0.f;

    load_stage(0, 0);
    asm volatile("cp.async.commit_group;" ::: "memory");
    load_stage(1, 1);
    asm volatile("cp.async.commit_group;" ::: "memory");

    const int a_lrow = lane & 15;
    const int a_chi = lane >> 4;
    const int b_lrow = (lane & 7) + ((lane >> 4) << 3);
    const int b_chi = (lane >> 3) & 1;

    constexpr int KT = KK >> 6;
    // rotating state: cur = kt%3 (starts 0), ns = (kt+2)%3 (starts 2); pointers advance by 64.
    int cur = 0, ns = 2;
    const __nv_bfloat16* pag = Ag + 2 * 64;
    const __nv_bfloat16* pbg = Bg + 2 * 64;
#pragma unroll 1
    for (int kt = 0; kt < KT; kt++) {
        asm volatile("cp.async.wait_group 1;" ::: "memory");
        __syncthreads();

        const bool pf = (kt + 2 < KT);
        const uint32_t pa_s = stA[ns];
        const uint32_t pb_s = stB[ns];

        const uint32_t sA = sbase + cur * GSTAGE_BYTES;
        const uint32_t sB = sA + GSTG * GSTAGE_BYTES;
#pragma unroll
        for (int ks = 0; ks < 4; ks++) {
            uint32_t af[4][4], bfr[4][2];
#pragma unroll
            for (int mi = 0; mi < 4; mi++) {
                int row = wm + mi * 16 + a_lrow;
                int cc = ks * 2 + a_chi;
                ldsm4(af[mi], sA + row * 128 + ((cc ^ (row & 7)) * 16));
            }
#pragma unroll
            for (int j = 0; j < 2; j++) {
                int row = wn + j * 16 + b_lrow;
                int cc = ks * 2 + b_chi;
                uint32_t rr[4];
                ldsm4(rr, sB + row * 128 + ((cc ^ (row & 7)) * 16));
                bfr[j * 2][0] = rr[0]; bfr[j * 2][1] = rr[1];
                bfr[j * 2 + 1][0] = rr[2]; bfr[j * 2 + 1][1] = rr[3];
            }
            if (pf) {
                cp16(pa_s + ks * 32 * 128, pag + (size_t)(ks * 32) * KK);
                cp16(pb_s + ks * 32 * 128, pbg + (size_t)(ks * 32) * KK);
            }
#pragma unroll
            for (int mi = 0; mi < 4; mi++)
#pragma unroll
                for (int ni = 0; ni < 4; ni++) mma16816(acc[mi][ni], af[mi], bfr[ni]);
        }
        asm volatile("cp.async.commit_group;" ::: "memory");
        pag += 64; pbg += 64;
        cur = (cur == GSTG - 1) ? 0 : cur + 1;
        ns = (ns == GSTG - 1) ? 0 : ns + 1;
    }

    const float QSCALE = 0.25f * LOG2E;
#pragma unroll
    for (int mi = 0; mi < 4; mi++) {
        int r0 = bm * 128 + wm + mi * 16 + gid;
#pragma unroll
        for (int ni = 0; ni < 4; ni++) {
            int col = bn * 128 + wn + ni * 8 + tig * 2;
            if (MODE == 1) {
                size_t i0 = (size_t)r0 * DD + col;
                size_t i1 = (size_t)(r0 + 8) * DD + col;
                float2 v0 = make_float2(acc[mi][ni][0] + resid[i0], acc[mi][ni][1] + resid[i0 + 1]);
                float2 v1 = make_float2(acc[mi][ni][2] + resid[i1], acc[mi][ni][3] + resid[i1 + 1]);
                *(float2*)&Cf[i0] = v0;
                *(float2*)&Cf[i1] = v1;
            } else {
                if (bn < 2) {
                    float f = (bn == 0) ? QSCALE : 1.f;
                    *(__nv_bfloat162*)&qk[(size_t)r0 * 256 + col] =
                        __floats2bfloat162_rn(acc[mi][ni][0] * f, acc[mi][ni][1] * f);
                    *(__nv_bfloat162*)&qk[(size_t)(r0 + 8) * 256 + col] =
                        __floats2bfloat162_rn(acc[mi][ni][2] * f, acc[mi][ni][3] * f);
                } else {
                    int e = (col - 256) >> 1;
                    float v0 = acc[mi][ni][0] * gelu_exact(acc[mi][ni][1]);
                    float v1 = acc[mi][ni][2] * gelu_exact(acc[mi][ni][3]);
                    if (e < 1024) {
                        concat[(size_t)r0 * EXPD + e] = __float2bfloat16(v0);
                        concat[(size_t)(r0 + 8) * EXPD + e] = __float2bfloat16(v1);
                    } else {
                        vbuf[(size_t)r0 * DD + e - 1024] = __float2half(v0);
                        vbuf[(size_t)(r0 + 8) * DD + e - 1024] = __float2half(v1);
                    }
                }
            }
        }
    }
}

// ---------------- flash attention (round-14 best, unchanged) ----------------
#define AKS_B 6144                         // Ks stage: 128 rows * 48B
#define AVS_B 32768                        // Vs stage: 128 rows * 256B
#define AST_B (AKS_B + AVS_B)
#define ATT_SMEM (2 * AST_B)               // 77824

__global__ __launch_bounds__(256, 1) void attn_kernel(const __nv_bfloat16* __restrict__ qk,
                                                      const __half* __restrict__ vbuf,
                                                      __nv_bfloat16* __restrict__ concat,
                                                      const float* __restrict__ pbm_p,
                                                      const int* __restrict__ fi_p,
                                                      const int* __restrict__ li_p) {
    extern __shared__ __align__(16) char asmem[];
    const int tid = threadIdx.x, warp = tid >> 5, lane = tid & 31;
    const int gid = lane >> 2, tig = lane & 3;
    const int bh = blockIdx.y, b = bh >> 3, h = bh & 7;
    const int qch = blockIdx.x;
    const int qbase = qch * 128;
    float pbm = *pbm_p;
    const float sp_l2 = (fmaxf(pbm, 0.f) + log1pf(expf(-fabsf(pbm)))) * LOG2E;
    int fi = *fi_p; if (fi >= SS) fi = 0;
    int li = *li_p; if (li >= SS) li = 0;

    const uint32_t abase = (uint32_t)__cvta_generic_to_shared(asmem);

    const int i0 = qbase + warp * 16 + gid;
    const int i1 = i0 + 8;
    uint32_t qa[4];
    {
        const size_t base = ((size_t)(b * SS + i0)) * 256 + h * 16 + tig * 2;
        qa[0] = *(const uint32_t*)&qk[base];
        qa[1] = *(const uint32_t*)&qk[base + 8 * 256];
        qa[2] = *(const uint32_t*)&qk[base + 8];
        qa[3] = *(const uint32_t*)&qk[base + 8 * 256 + 8];
    }
    float m0 = -1e30f, m1 = -1e30f;
    float o[16][4];
#pragma unroll
    for (int ni = 0; ni < 16; ni++)
#pragma unroll
        for (int r = 0; r < 4; r++) o[ni][r] = 0.f;
    float o_l[4] = {0.f, 0.f, 0.f, 0.f};  // ones-column: row sums

    const int qmax = qbase + 127;
    const int l15 = lane & 15, lhi = lane >> 4;
    const int kb = (lane & 7) + ((lane >> 4) << 3);   // QK B-frag ldsm row
    const int kcc = (lane >> 3) & 1;                  // QK B-frag 16B chunk

    int list[8];
    int n = 0;
#pragma unroll
    for (int kc = 0; kc < 8; kc++) {
        int kmin = kc * 128;
        if (kmin <= qmax || ((qmax >= fi) && (kmin + 127 >= li))) list[n++] = kc;
    }

    const int lrow = tid >> 1, lhalf = tid & 1;
    auto load_chunk = [&](int st, int kmin) {
        uint32_t ks = abase + st * AST_B;
        uint32_t vs = ks + AKS_B;
        cp16(ks + lrow * 48 + lhalf * 16,
             &qk[((size_t)(b * SS + kmin + lrow)) * 256 + 128 + h * 16 + lhalf * 8]);
        const __half* src = &vbuf[((size_t)(b * SS + kmin + lrow)) * DD + h * 128 + lhalf * 64];
        uint32_t drow = vs + lrow * 256;
        int rsw = lrow & 15;
#pragma unroll
        for (int j = 0; j < 8; j++) {
            int cc = lhalf * 8 + j;
            cp16(drow + ((cc ^ rsw) << 4), src + j * 8);
        }
    };

    const uint32_t bones[2] = {0x3C003C00u, 0x3C003C00u};  // f16 ones

    load_chunk(0, list[0] * 128);
    asm volatile("cp.async.commit_group;" ::: "memory");

    for (int t = 0; t < n; t++) {
        const int kc = list[t];
        const int kmin = kc * 128;
        const int st = t & 1;
        if (t + 1 < n) {
            load_chunk((t + 1) & 1, list[t + 1] * 128);
            asm volatile("cp.async.commit_group;" ::: "memory");
            asm volatile("cp.async.wait_group 1;" ::: "memory");
        } else {
            asm volatile("cp.async.wait_group 0;" ::: "memory");
        }
        __syncthreads();

        const uint32_t ksb = abase + st * AST_B;
        const uint32_t vsb = ksb + AKS_B;

        // QK^T: B fragments via ldmatrix.x4 over 48B-stride K rows
        float sc[16][4];
#pragma unroll
        for (int ni2 = 0; ni2 < 8; ni2++) {
            uint32_t rr[4];
            ldsm4(rr, ksb + (ni2 * 16 + kb) * 48 + kcc * 16);
#pragma unroll
            for (int tt = 0; tt < 2; tt++) {
                const int ni = 2 * ni2 + tt;
                sc[ni][0] = sc[ni][1] = sc[ni][2] = sc[ni][3] = 0.f;
                uint32_t bf[2] = {rr[2 * tt], rr[2 * tt + 1]};
                mma16816(sc[ni], qa, bf);
            }
        }

        float rmax0 = -1e30f, rmax1 = -1e30f;
        if (kc < qch) {
            float b0 = sp_l2 * (float)(kmin + tig * 2 - i0);
            float b1 = b0 + sp_l2;
            float b2 = b0 - 8.f * sp_l2;
            float b3 = b2 + sp_l2;
            const float d8 = 8.f * sp_l2;
#pragma unroll
            for (int ni = 0; ni < 16; ni++) {
                sc[ni][0] += b0; sc[ni][1] += b1; sc[ni][2] += b2; sc[ni][3] += b3;
                rmax0 = fmaxf(rmax0, fmaxf(sc[ni][0], sc[ni][1]));
                rmax1 = fmaxf(rmax1, fmaxf(sc[ni][2], sc[ni][3]));
                b0 += d8; b1 += d8; b2 += d8; b3 += d8;
            }
        } else {
#pragma unroll
            for (int ni = 0; ni < 16; ni++) {
                int jc = kmin + ni * 8 + tig * 2;
#pragma unroll
                for (int r = 0; r < 4; r++) {
                    int j = jc + (r & 1);
                    int i = (r < 2) ? i0 : i1;
                    bool ok = (j <= i) || ((i >= fi) && (j >= li));
                    float s = ok ? fmaf(sp_l2, (float)(j - i), sc[ni][r]) : -1e30f;
                    sc[ni][r] = s;
                    if (r < 2) rmax0 = fmaxf(rmax0, s);
                    else rmax1 = fmaxf(rmax1, s);
                }
            }
        }
        rmax0 = fmaxf(rmax0, __shfl_xor_sync(0xffffffffu, rmax0, 1));
        rmax0 = fmaxf(rmax0, __shfl_xor_sync(0xffffffffu, rmax0, 2));
        rmax1 = fmaxf(rmax1, __shfl_xor_sync(0xffffffffu, rmax1, 1));
        rmax1 = fmaxf(rmax1, __shfl_xor_sync(0xffffffffu, rmax1, 2));
        float mn0 = fmaxf(m0, rmax0), mn1 = fmaxf(m1, rmax1);
        float cor0 = exp2f(m0 - mn0), cor1 = exp2f(m1 - mn1);
        m0 = mn0; m1 = mn1;
#pragma unroll
        for (int ni = 0; ni < 16; ni++) {
            o[ni][0] *= cor0; o[ni][1] *= cor0; o[ni][2] *= cor1; o[ni][3] *= cor1;
        }
        o_l[0] *= cor0; o_l[1] *= cor0; o_l[2] *= cor1; o_l[3] *= cor1;

        uint32_t pk0[16], pk1[16];
#pragma unroll
        for (int ni = 0; ni < 16; ni++) {
            pk0[ni] = exp2_f16x2(sc[ni][0] - m0, sc[ni][1] - m0);
            pk1[ni] = exp2_f16x2(sc[ni][2] - m1, sc[ni][3] - m1);
        }

        const uint32_t vrow = vsb + l15 * 256;
#pragma unroll
        for (int ks = 0; ks < 8; ks++) {
            uint32_t pa[4] = {pk0[2 * ks], pk1[2 * ks], pk0[2 * ks + 1], pk1[2 * ks + 1]};
            mma16816h(o_l, pa, bones);
            const uint32_t kofs = vrow + ks * 4096;
#pragma unroll
            for (int ni2 = 0; ni2 < 8; ni2++) {
                uint32_t rr[4];
                ldsm4t(rr, kofs + (((ni2 * 2 + lhi) ^ l15) << 4));
                uint32_t b0[2] = {rr[0], rr[1]};
                uint32_t b1[2] = {rr[2], rr[3]};
                mma16816h(o[2 * ni2], pa, b0);
                mma16816h(o[2 * ni2 + 1], pa, b1);
            }
        }
        __syncthreads();
    }

    float inv0 = 1.f / o_l[0], inv1 = 1.f / o_l[2];
#pragma unroll
    for (int ni = 0; ni < 16; ni++) {
        int col = 1024 + h * 128 + ni * 8 + tig * 2;
        *(__nv_bfloat162*)&concat[((size_t)(b * SS) + i0) * EXPD + col] =
            __floats2bfloat162_rn(o[ni][0] * inv0, o[ni][1] * inv0);
        *(__nv_bfloat162*)&concat[((size_t)(b * SS) + i1) * EXPD + col] =
            __floats2bfloat162_rn(o[ni][2] * inv1, o[ni][3] * inv1);
    }
}

// ---------------- launch ----------------
extern "C" void kernel_launch(void* const* d_in, const int* in_sizes, int n_in,
                              void* d_out, int out_size) {
    const float* x = (const float*)d_in[0];
    const float* norm_w = (const float*)d_in[1];
    const float* expand_w = (const float*)d_in[2];
    const float* project_w = (const float*)d_in[3];
    const float* pbm = (const float*)d_in[4];
    const int* fi = (const int*)d_in[5];
    const int* li = (const int*)d_in[6];
    float* out = (float*)d_out;

    void *p_xn, *p_qk, *p_concat, *p_v, *p_wexp, *p_wproj;
    cudaGetSymbolAddress(&p_xn, g_xn);
    cudaGetSymbolAddress(&p_qk, g_qk);
    cudaGetSymbolAddress(&p_concat, g_concat);
    cudaGetSymbolAddress(&p_v, g_v);
    cudaGetSymbolAddress(&p_wexp, g_wexp);
    cudaGetSymbolAddress(&p_wproj, g_wproj);
    __nv_bfloat16* xn = (__nv_bfloat16*)p_xn;
    __nv_bfloat16* qk = (__nv_bfloat16*)p_qk;
    __nv_bfloat16* concat = (__nv_bfloat16*)p_concat;
    __half* vb = (__half*)p_v;
    __nv_bfloat16* wexp = (__nv_bfloat16*)p_wexp;
    __nv_bfloat16* wproj = (__nv_bfloat16*)p_wproj;

    cudaFuncSetAttribute(gemm_bf16<0, 1024>, cudaFuncAttributeMaxDynamicSharedMemorySize, GSMEM_BYTES);
    cudaFuncSetAttribute(gemm_bf16<1, 2048>, cudaFuncAttributeMaxDynamicSharedMemorySize, GSMEM_BYTES);
    cudaFuncSetAttribute(attn_kernel, cudaFuncAttributeMaxDynamicSharedMemorySize, ATT_SMEM);

    // merged weight convert (wexp reorder + wproj)
    cvt_all_kernel<<<(WEXP4 + WPROJ4 + 255) / 256, 256>>>(expand_w, project_w, wexp, wproj);

    // layernorm
    ln_kernel<<<NROWS, 256>>>(x, norm_w, xn);

    // expand GEMM fused with geglu: qk (q pre-scaled) + concat[:, :1024] + vbuf (f16)
    gemm_bf16<0, 1024><<<dim3(EOUT / 128, NROWS / 128), 256, GSMEM_BYTES>>>(
        xn, wexp, qk, concat, vb, nullptr, nullptr);

    // attention -> concat[:, 1024:2048]
    attn_kernel<<<dim3(SS / 128, BB * HH), 256, ATT_SMEM>>>(qk, vb, concat, pbm, fi, li);

    // project GEMM + residual: out = concat @ wproj^T + x
    gemm_bf16<1, 2048><<<dim3(DD / 128, NROWS / 128), 256, GSMEM_BYTES>>>(
        concat, wproj, nullptr, nullptr, nullptr, x, out);
}